// round 7
// baseline (speedup 1.0000x reference)
#include <cuda_runtime.h>
#include <math.h>
#include <stdint.h>

#define BATCH 64
#define NN    512
#define HH    256
#define DNODE 38
#define TOKENS (BATCH*NN)
#define GRID  128
#define NTILE (TOKENS/32)     // 1024 lidar tiles

// ---------------- scratch (device globals) ----------------------------------
__device__ float g_node[(size_t)TOKENS * DNODE];
__device__ float g_S0part[NTILE][DNODE];
__device__ float g_S1[BATCH * HH];
__device__ float g_h1[(size_t)(64 + TOKENS) * HH];
__device__ unsigned g_farmask[(size_t)TOKENS * 16];
__device__ int g_ndH[GRID];
__device__ unsigned short g_dirtyJH[GRID][256];
__device__ unsigned g_bar[8];

// ---------------- smem union --------------------------------------------------
union SmemU {
    struct { float lid[32][20]; float hid[32][256]; float nodeb[32][38]; } L;   // ~40KB
    struct { float px[NN]; float py[NN]; int wcnt[8]; } F;                      // ~4.2KB
    struct { float X[4][256]; float T1[4][256]; float T2[4][256];
             float x38[4][40]; float red[16]; float out5[4][5]; } R;            // ~13KB
};

// ---------------- grid barrier (all GRID blocks co-resident) ------------------
__device__ __forceinline__ void gbar(int slot) {
    __syncthreads();
    if (threadIdx.x == 0) {
        __threadfence();
        atomicAdd(&g_bar[slot], 1u);
        while (((volatile unsigned*)g_bar)[slot] < (unsigned)GRID) __nanosleep(64);
        __threadfence();
    }
    __syncthreads();
}

__device__ __forceinline__ int find_dirty(int e, int& b) {
    int acc = 0;
    for (int h = 0; h < GRID; h++) {
        int c = g_ndH[h];
        if (e < acc + c) { b = h >> 1; return b * NN + g_dirtyJH[h][e - acc]; }
        acc += c;
    }
    return -1;
}

// ---------------- THE kernel --------------------------------------------------
__global__ __launch_bounds__(256)
void chain_kernel(const float* __restrict__ data,
                  const float* __restrict__ lw1, const float* __restrict__ lb1,
                  const float* __restrict__ lw2, const float* __restrict__ lb2,
                  const float* __restrict__ g1w1, const float* __restrict__ g1b1,
                  const float* __restrict__ g1w2, const float* __restrict__ g1b2,
                  const float* __restrict__ g2w1, const float* __restrict__ g2b1,
                  const float* __restrict__ g2w2, const float* __restrict__ g2b2,
                  const float* __restrict__ t_in_w, const float* __restrict__ t_in_b,
                  const float* __restrict__ t_out_w, const float* __restrict__ t_out_b,
                  const float* __restrict__ t_ln1_g, const float* __restrict__ t_ln1_b,
                  const float* __restrict__ t_ff1_w, const float* __restrict__ t_ff1_b,
                  const float* __restrict__ t_ff2_w, const float* __restrict__ t_ff2_b,
                  const float* __restrict__ t_ln2_g, const float* __restrict__ t_ln2_b,
                  const float* __restrict__ fc_w, const float* __restrict__ fc_b,
                  float* __restrict__ out)
{
    __shared__ SmemU sm;
    __shared__ int s_nD;
    int tid = threadIdx.x, w = tid >> 5, lane = tid & 31;

    // ======================= P-1: lidar MLP + node + S0 partials =============
    {
        float wreg[20];
        #pragma unroll
        for (int k = 0; k < 20; k++) wreg[k] = lw1[tid * 20 + k];
        float b1v = lb1[tid];
        for (int tile = blockIdx.x; tile < NTILE; tile += GRID) {
            int tok0 = tile * 32;
            __syncthreads();
            for (int idx = tid; idx < 32 * 20; idx += 256) {
                int t = idx / 20, c = idx % 20;
                sm.L.lid[t][c] = data[(size_t)(tok0 + t) * DNODE + 18 + c];
            }
            for (int idx = tid; idx < 32 * 18; idx += 256) {
                int t = idx / 18, c = idx % 18;
                sm.L.nodeb[t][c] = data[(size_t)(tok0 + t) * DNODE + c];
            }
            __syncthreads();
            #pragma unroll 4
            for (int t = 0; t < 32; t++) {
                float acc = b1v;
                #pragma unroll
                for (int k = 0; k < 20; k++) acc += wreg[k] * sm.L.lid[t][k];
                sm.L.hid[t][tid] = fmaxf(acc, 0.0f);
            }
            __syncthreads();
            #pragma unroll
            for (int tt = 0; tt < 4; tt++) {
                int t = w * 4 + tt;
                for (int o = 0; o < 20; o++) {
                    const float* wr = lw2 + o * 256;
                    float s = 0.0f;
                    #pragma unroll
                    for (int q = 0; q < 8; q++)
                        s += sm.L.hid[t][lane + 32 * q] * wr[lane + 32 * q];
                    #pragma unroll
                    for (int off = 16; off; off >>= 1) s += __shfl_xor_sync(~0u, s, off);
                    if (!lane) sm.L.nodeb[t][18 + o] = fmaxf(s + lb2[o], 0.0f);
                }
            }
            __syncthreads();
            for (int idx = tid; idx < 32 * 38; idx += 256) {
                int t = idx / 38, c = idx % 38;
                g_node[(size_t)(tok0 + t) * DNODE + c] = sm.L.nodeb[t][c];
            }
            if (tid < DNODE) {
                float s = 0.0f;
                #pragma unroll 8
                for (int t = 0; t < 32; t++) s += sm.L.nodeb[t][tid];
                g_S0part[tile][tid] = s;
            }
        }
    }
    gbar(0);

    // ======================= P0: far detect (2 blocks per batch) =============
    {
        int b = blockIdx.x >> 1, half = blockIdx.x & 1;
        const float* db = data + (size_t)b * NN * DNODE;
        for (int i = tid; i < NN; i += 256) {
            sm.F.px[i] = db[(size_t)i * DNODE + 0];
            sm.F.py[i] = db[(size_t)i * DNODE + 1];
        }
        __syncthreads();
        unsigned short myj[32];
        int mycnt = 0;
        int j0 = half * 256 + w * 32;
        for (int jj = 0; jj < 32; jj++) {
            int j = j0 + jj;
            float xj = sm.F.px[j], yj = sm.F.py[j];
            unsigned mm[16], any = 0;
            #pragma unroll
            for (int wd = 0; wd < 16; wd++) {
                int i = wd * 32 + lane;
                float dx = sm.F.px[i] - xj, dy = sm.F.py[i] - yj;
                float d2 = dx * dx + dy * dy;
                bool near_ = d2 <= 100.0f;
                if (d2 > 99.0f && d2 < 101.0f) near_ = (sqrtf(d2) <= 10.0f);
                bool far = (i != j) && !near_;
                mm[wd] = __ballot_sync(~0u, far);
                any |= mm[wd];
            }
            if (any) {
                if (!lane) {
                    #pragma unroll
                    for (int wd = 0; wd < 16; wd++)
                        g_farmask[((size_t)(b * NN + j)) * 16 + wd] = mm[wd];
                    myj[mycnt] = (unsigned short)j;
                }
                mycnt++;
            }
        }
        if (!lane) sm.F.wcnt[w] = mycnt;
        __syncthreads();
        if (tid == 0) {
            int tot = 0;
            for (int q = 0; q < 8; q++) tot += sm.F.wcnt[q];
            g_ndH[blockIdx.x] = tot;
        }
        // ordered copy: warp w's entries after warps < w
        if (!lane && mycnt) {
            int off = 0;
            for (int q = 0; q < w; q++) off += sm.F.wcnt[q];
            for (int k = 0; k < mycnt; k++)
                g_dirtyJH[blockIdx.x][off + k] = myj[k];
        }
    }
    gbar(1);
    if (tid == 0) {
        int a = 0;
        for (int h = 0; h < GRID; h++) a += g_ndH[h];
        s_nD = a;
    }
    __syncthreads();
    int nD = s_nD;

    // ---------------- shared-memory GEMV helpers -----------------------------
    auto gemv4 = [&](const float (*src)[256],
                     float* d0, float* d1, float* d2, float* d3,
                     const float* W, const float* bias, bool relu) {
        float bb = bias[tid];
        float a0 = bb, a1 = bb, a2 = bb, a3 = bb;
        const float4* wr = (const float4*)(W + (size_t)tid * HH);
        const float4* s0 = (const float4*)src[0];
        const float4* s1 = (const float4*)src[1];
        const float4* s2 = (const float4*)src[2];
        const float4* s3 = (const float4*)src[3];
        #pragma unroll 8
        for (int q = 0; q < 64; q++) {
            float4 wv = wr[q];
            float4 v0 = s0[q], v1 = s1[q], v2 = s2[q], v3 = s3[q];
            a0 += wv.x * v0.x + wv.y * v0.y + wv.z * v0.z + wv.w * v0.w;
            a1 += wv.x * v1.x + wv.y * v1.y + wv.z * v1.z + wv.w * v1.w;
            a2 += wv.x * v2.x + wv.y * v2.y + wv.z * v2.z + wv.w * v2.w;
            a3 += wv.x * v3.x + wv.y * v3.y + wv.z * v3.z + wv.w * v3.w;
        }
        if (relu) {
            a0 = fmaxf(a0, 0.f); a1 = fmaxf(a1, 0.f);
            a2 = fmaxf(a2, 0.f); a3 = fmaxf(a3, 0.f);
        }
        d0[tid] = a0; d1[tid] = a1; d2[tid] = a2; d3[tid] = a3;
        __syncthreads();
    };
    auto gemv1 = [&](const float* src, float* dst,
                     const float* W, const float* bias, bool relu) {
        float a = bias[tid];
        const float4* wr = (const float4*)(W + (size_t)tid * HH);
        const float4* s0 = (const float4*)src;
        #pragma unroll 8
        for (int q = 0; q < 64; q++) {
            float4 wv = wr[q];
            float4 v0 = s0[q];
            a += wv.x * v0.x + wv.y * v0.y + wv.z * v0.z + wv.w * v0.w;
        }
        dst[tid] = relu ? fmaxf(a, 0.f) : a;
        __syncthreads();
    };
    auto ln_row = [&](float* xv, const float* yv, const float* gg, const float* bb) {
        float v = xv[tid] + yv[tid];
        float s = v;
        #pragma unroll
        for (int off = 16; off; off >>= 1) s += __shfl_xor_sync(~0u, s, off);
        if (!lane) sm.R.red[w] = s;
        __syncthreads();
        float tot = 0.f;
        #pragma unroll
        for (int q = 0; q < 8; q++) tot += sm.R.red[q];
        float mean = tot * (1.0f / 256.0f);
        float d = v - mean;
        float s2 = d * d;
        #pragma unroll
        for (int off = 16; off; off >>= 1) s2 += __shfl_xor_sync(~0u, s2, off);
        if (!lane) sm.R.red[8 + w] = s2;
        __syncthreads();
        float tot2 = 0.f;
        #pragma unroll
        for (int q = 0; q < 8; q++) tot2 += sm.R.red[8 + q];
        float var = tot2 * (1.0f / 256.0f);
        xv[tid] = d / sqrtf(var + 1e-5f) * gg[tid] + bb[tid];
        __syncthreads();
    };

    // ======================= P1: GIN1 ========================================
    {
        int U = 16 + nD;
        for (int u = blockIdx.x; u < U; u += GRID) {
            if (u < 16) {
                int b0 = u * 4;
                for (int idx = tid; idx < 4 * DNODE; idx += 256) {
                    int r = idx / DNODE, c = idx % DNODE;
                    float s = 0.f;
                    #pragma unroll
                    for (int p = 0; p < 16; p++) s += g_S0part[(b0 + r) * 16 + p][c];
                    sm.R.x38[r][c] = s;
                }
                __syncthreads();
                float a0 = g1b1[tid], a1 = a0, a2 = a0, a3 = a0;
                #pragma unroll
                for (int k = 0; k < DNODE; k++) {
                    float wk = g1w1[tid * DNODE + k];
                    a0 += wk * sm.R.x38[0][k];
                    a1 += wk * sm.R.x38[1][k];
                    a2 += wk * sm.R.x38[2][k];
                    a3 += wk * sm.R.x38[3][k];
                }
                sm.R.T1[0][tid] = fmaxf(a0, 0.f);
                sm.R.T1[1][tid] = fmaxf(a1, 0.f);
                sm.R.T1[2][tid] = fmaxf(a2, 0.f);
                sm.R.T1[3][tid] = fmaxf(a3, 0.f);
                __syncthreads();
                gemv4(sm.R.T1,
                      &g_h1[(size_t)(b0 + 0) * HH], &g_h1[(size_t)(b0 + 1) * HH],
                      &g_h1[(size_t)(b0 + 2) * HH], &g_h1[(size_t)(b0 + 3) * HH],
                      g1w2, g1b2, true);
            } else {
                int b;
                int tok = find_dirty(u - 16, b);
                if (tid < DNODE) {
                    float v = 0.f;
                    #pragma unroll
                    for (int p = 0; p < 16; p++) v += g_S0part[b * 16 + p][tid];
                    for (int wd = 0; wd < 16; wd++) {
                        unsigned m = g_farmask[(size_t)tok * 16 + wd];
                        while (m) {
                            int i = wd * 32 + __ffs(m) - 1; m &= m - 1;
                            v -= g_node[((size_t)b * NN + i) * DNODE + tid];
                        }
                    }
                    sm.R.x38[0][tid] = v;
                }
                __syncthreads();
                float a = g1b1[tid];
                #pragma unroll
                for (int k = 0; k < DNODE; k++)
                    a += g1w1[tid * DNODE + k] * sm.R.x38[0][k];
                sm.R.T1[0][tid] = fmaxf(a, 0.f);
                __syncthreads();
                gemv1(sm.R.T1[0], &g_h1[(size_t)(64 + tok) * HH], g1w2, g1b2, true);
            }
        }
    }
    gbar(2);

    // ======================= P2: S1 reduce ===================================
    for (int b = blockIdx.x; b < BATCH; b += GRID) {
        float uv = g_h1[(size_t)b * HH + tid];
        int nd = g_ndH[2 * b] + g_ndH[2 * b + 1];
        float s = (float)(NN - nd) * uv;
        for (int h = 2 * b; h <= 2 * b + 1; h++) {
            int c = g_ndH[h];
            for (int k = 0; k < c; k++) {
                int tok = b * NN + g_dirtyJH[h][k];
                s += g_h1[(size_t)(64 + tok) * HH + tid];
            }
        }
        g_S1[b * HH + tid] = s;
    }
    gbar(3);

    // ======================= P3: rest on uniform rows (4 batches / block) ====
    for (int u = blockIdx.x; u < 16; u += GRID) {
        int b0 = u * 4;
        #pragma unroll
        for (int r = 0; r < 4; r++) sm.R.X[r][tid] = g_S1[(b0 + r) * HH + tid];
        __syncthreads();
        gemv4(sm.R.X, sm.R.T1[0], sm.R.T1[1], sm.R.T1[2], sm.R.T1[3], g2w1, g2b1, true);
        gemv4(sm.R.T1, sm.R.X[0], sm.R.X[1], sm.R.X[2], sm.R.X[3], g2w2, g2b2, true);
        for (int l = 0; l < 2; l++) {
            const float* Wv  = t_in_w + (size_t)l * 768 * HH + (size_t)512 * HH;
            const float* bv  = t_in_b + (size_t)l * 768 + 512;
            const float* Wo  = t_out_w + (size_t)l * HH * HH;
            const float* bo  = t_out_b + (size_t)l * HH;
            const float* W1  = t_ff1_w + (size_t)l * HH * HH;
            const float* b1  = t_ff1_b + (size_t)l * HH;
            const float* W2  = t_ff2_w + (size_t)l * HH * HH;
            const float* b2  = t_ff2_b + (size_t)l * HH;
            gemv4(sm.R.X,  sm.R.T1[0], sm.R.T1[1], sm.R.T1[2], sm.R.T1[3], Wv, bv, false);
            gemv4(sm.R.T1, sm.R.T2[0], sm.R.T2[1], sm.R.T2[2], sm.R.T2[3], Wo, bo, false);
            for (int r = 0; r < 4; r++)
                ln_row(sm.R.X[r], sm.R.T2[r],
                       t_ln1_g + (size_t)l * HH, t_ln1_b + (size_t)l * HH);
            gemv4(sm.R.X,  sm.R.T1[0], sm.R.T1[1], sm.R.T1[2], sm.R.T1[3], W1, b1, true);
            gemv4(sm.R.T1, sm.R.T2[0], sm.R.T2[1], sm.R.T2[2], sm.R.T2[3], W2, b2, false);
            for (int r = 0; r < 4; r++)
                ln_row(sm.R.X[r], sm.R.T2[r],
                       t_ln2_g + (size_t)l * HH, t_ln2_b + (size_t)l * HH);
        }
        if (w < 5) {
            const float* wr = fc_w + w * HH;
            for (int r = 0; r < 4; r++) {
                float s = 0.f;
                #pragma unroll
                for (int q = 0; q < 8; q++) s += sm.R.X[r][lane + 32 * q] * wr[lane + 32 * q];
                #pragma unroll
                for (int off = 16; off; off >>= 1) s += __shfl_xor_sync(~0u, s, off);
                if (!lane) sm.R.out5[r][w] = s + fc_b[w];
            }
        }
        __syncthreads();
        for (int f = tid; f < 4 * NN * 5; f += 256) {
            int r = f / (NN * 5);
            int rem = f - r * NN * 5;
            int t = rem / 5, c = rem - t * 5;
            out[((size_t)(b0 + r) * NN + t) * 5 + c] = sm.R.out5[r][c];
        }
        __syncthreads();
    }
    gbar(4);

    // ======================= P4: rest on dirty rows (overwrite) ==============
    for (int e = blockIdx.x; e < nD; e += GRID) {
        int b;
        int tok = find_dirty(e, b);
        float v = g_S1[b * HH + tid];
        for (int wd = 0; wd < 16; wd++) {
            unsigned m = g_farmask[(size_t)tok * 16 + wd];
            while (m) {
                int i = wd * 32 + __ffs(m) - 1; m &= m - 1;
                v -= g_h1[(size_t)(64 + b * NN + i) * HH + tid];
            }
        }
        sm.R.X[0][tid] = v;
        __syncthreads();
        gemv1(sm.R.X[0], sm.R.T1[0], g2w1, g2b1, true);
        gemv1(sm.R.T1[0], sm.R.X[0], g2w2, g2b2, true);
        for (int l = 0; l < 2; l++) {
            const float* Wv  = t_in_w + (size_t)l * 768 * HH + (size_t)512 * HH;
            const float* bv  = t_in_b + (size_t)l * 768 + 512;
            const float* Wo  = t_out_w + (size_t)l * HH * HH;
            const float* bo  = t_out_b + (size_t)l * HH;
            const float* W1  = t_ff1_w + (size_t)l * HH * HH;
            const float* b1  = t_ff1_b + (size_t)l * HH;
            const float* W2  = t_ff2_w + (size_t)l * HH * HH;
            const float* b2  = t_ff2_b + (size_t)l * HH;
            gemv1(sm.R.X[0],  sm.R.T1[0], Wv, bv, false);
            gemv1(sm.R.T1[0], sm.R.T2[0], Wo, bo, false);
            ln_row(sm.R.X[0], sm.R.T2[0], t_ln1_g + (size_t)l * HH, t_ln1_b + (size_t)l * HH);
            gemv1(sm.R.X[0],  sm.R.T1[0], W1, b1, true);
            gemv1(sm.R.T1[0], sm.R.T2[0], W2, b2, false);
            ln_row(sm.R.X[0], sm.R.T2[0], t_ln2_g + (size_t)l * HH, t_ln2_b + (size_t)l * HH);
        }
        if (w < 5) {
            const float* wr = fc_w + w * HH;
            float s = 0.f;
            #pragma unroll
            for (int q = 0; q < 8; q++) s += sm.R.X[0][lane + 32 * q] * wr[lane + 32 * q];
            #pragma unroll
            for (int off = 16; off; off >>= 1) s += __shfl_xor_sync(~0u, s, off);
            if (!lane) sm.R.out5[0][w] = s + fc_b[w];
        }
        __syncthreads();
        if (tid < 5) out[(size_t)tok * 5 + tid] = sm.R.out5[0][tid];
        __syncthreads();
    }
}

// ---------------- launch ------------------------------------------------------
extern "C" void kernel_launch(void* const* d_in, const int* in_sizes, int n_in,
                              void* d_out, int out_size)
{
    const float* data   = (const float*)d_in[0];
    const float* lw1    = (const float*)d_in[1];
    const float* lb1    = (const float*)d_in[2];
    const float* lw2    = (const float*)d_in[3];
    const float* lb2    = (const float*)d_in[4];
    const float* g1w1   = (const float*)d_in[5];
    const float* g1b1   = (const float*)d_in[6];
    const float* g1w2   = (const float*)d_in[7];
    const float* g1b2   = (const float*)d_in[8];
    const float* g2w1   = (const float*)d_in[9];
    const float* g2b1   = (const float*)d_in[10];
    const float* g2w2   = (const float*)d_in[11];
    const float* g2b2   = (const float*)d_in[12];
    const float* t_in_w = (const float*)d_in[13];
    const float* t_in_b = (const float*)d_in[14];
    const float* t_out_w= (const float*)d_in[15];
    const float* t_out_b= (const float*)d_in[16];
    const float* t_ln1_g= (const float*)d_in[17];
    const float* t_ln1_b= (const float*)d_in[18];
    const float* t_ff1_w= (const float*)d_in[19];
    const float* t_ff1_b= (const float*)d_in[20];
    const float* t_ff2_w= (const float*)d_in[21];
    const float* t_ff2_b= (const float*)d_in[22];
    const float* t_ln2_g= (const float*)d_in[23];
    const float* t_ln2_b= (const float*)d_in[24];
    const float* fc_w   = (const float*)d_in[25];
    const float* fc_b   = (const float*)d_in[26];
    float* out = (float*)d_out;

    void* barp;
    cudaGetSymbolAddress(&barp, g_bar);
    cudaMemsetAsync(barp, 0, sizeof(unsigned) * 8);

    chain_kernel<<<GRID, 256>>>(data, lw1, lb1, lw2, lb2,
                                g1w1, g1b1, g1w2, g1b2,
                                g2w1, g2b1, g2w2, g2b2,
                                t_in_w, t_in_b, t_out_w, t_out_b,
                                t_ln1_g, t_ln1_b, t_ff1_w, t_ff1_b,
                                t_ff2_w, t_ff2_b, t_ln2_g, t_ln2_b,
                                fc_w, fc_b, out);
    (void)in_sizes; (void)n_in; (void)out_size;
}

// round 8
// speedup vs baseline: 1.5954x; 1.5954x over previous
#include <cuda_runtime.h>
#include <math.h>
#include <stdint.h>

#define BATCH 64
#define NN    512
#define HH    256
#define DNODE 38
#define TOKENS (BATCH*NN)
#define NTILE (TOKENS/32)      // 1024 lidar tiles, 16 per batch

// ---------------- scratch (device globals) ----------------------------------
__device__ float g_node[(size_t)TOKENS * DNODE];
__device__ float g_S0part[NTILE][DNODE];
__device__ float g_h1[(size_t)(64 + TOKENS) * HH];
__device__ unsigned g_farmask[(size_t)TOKENS * 16];
__device__ int g_ndH[128];                       // per far-half-block dirty count
__device__ unsigned short g_dirtyJH[128][256];   // per far-half-block dirty j list
__device__ int g_slot[TOKENS];                   // -1 clean (memset 0xFF), else dirty

// ---------------- K1: lidar (blocks 0..1023) + far detect (1024..1151) ------
union SmemK1 {
    struct { float lid[32][20]; float hid[32][256]; float nodeb[32][38]; } L;
    struct { float px[NN]; float py[NN]; int wcnt[8]; } F;
};

__global__ __launch_bounds__(256)
void k1_kernel(const float* __restrict__ data,
               const float* __restrict__ lw1, const float* __restrict__ lb1,
               const float* __restrict__ lw2, const float* __restrict__ lb2)
{
    __shared__ SmemK1 sm;
    int tid = threadIdx.x, w = tid >> 5, lane = tid & 31;

    if (blockIdx.x < NTILE) {
        // ---------------- lidar MLP tile (32 tokens) ----------------
        int tok0 = blockIdx.x * 32;
        for (int idx = tid; idx < 32 * 20; idx += 256) {
            int t = idx / 20, c = idx % 20;
            sm.L.lid[t][c] = data[(size_t)(tok0 + t) * DNODE + 18 + c];
        }
        for (int idx = tid; idx < 32 * 18; idx += 256) {
            int t = idx / 18, c = idx % 18;
            sm.L.nodeb[t][c] = data[(size_t)(tok0 + t) * DNODE + c];
        }
        float wreg[20];
        #pragma unroll
        for (int k = 0; k < 20; k++) wreg[k] = lw1[tid * 20 + k];
        float b1v = lb1[tid];
        __syncthreads();

        #pragma unroll 4
        for (int t = 0; t < 32; t++) {
            float acc = b1v;
            #pragma unroll
            for (int k = 0; k < 20; k++) acc += wreg[k] * sm.L.lid[t][k];
            sm.L.hid[t][tid] = fmaxf(acc, 0.0f);
        }
        __syncthreads();

        #pragma unroll
        for (int tt = 0; tt < 4; tt++) {
            int t = w * 4 + tt;
            for (int o = 0; o < 20; o++) {
                const float* wr = lw2 + o * 256;
                float s = 0.0f;
                #pragma unroll
                for (int q = 0; q < 8; q++)
                    s += sm.L.hid[t][lane + 32 * q] * wr[lane + 32 * q];
                #pragma unroll
                for (int off = 16; off; off >>= 1) s += __shfl_xor_sync(~0u, s, off);
                if (!lane) sm.L.nodeb[t][18 + o] = fmaxf(s + lb2[o], 0.0f);
            }
        }
        __syncthreads();

        for (int idx = tid; idx < 32 * 38; idx += 256) {
            int t = idx / 38, c = idx % 38;
            g_node[(size_t)(tok0 + t) * DNODE + c] = sm.L.nodeb[t][c];
        }
        if (tid < DNODE) {
            float s = 0.0f;
            #pragma unroll 8
            for (int t = 0; t < 32; t++) s += sm.L.nodeb[t][tid];
            g_S0part[blockIdx.x][tid] = s;
        }
    } else {
        // ---------------- far-pair detect (2 half-blocks per batch) ----------
        int fb = blockIdx.x - NTILE;          // 0..127
        int b = fb >> 1, half = fb & 1;
        const float* db = data + (size_t)b * NN * DNODE;
        for (int i = tid; i < NN; i += 256) {
            sm.F.px[i] = db[(size_t)i * DNODE + 0];
            sm.F.py[i] = db[(size_t)i * DNODE + 1];
        }
        __syncthreads();
        unsigned short myj[32];
        int mycnt = 0;
        int j0 = half * 256 + w * 32;
        for (int jj = 0; jj < 32; jj++) {
            int j = j0 + jj;
            float xj = sm.F.px[j], yj = sm.F.py[j];
            unsigned mm[16], any = 0;
            #pragma unroll
            for (int wd = 0; wd < 16; wd++) {
                int i = wd * 32 + lane;
                float dx = sm.F.px[i] - xj, dy = sm.F.py[i] - yj;
                float d2 = dx * dx + dy * dy;
                bool near_ = d2 <= 100.0f;
                if (d2 > 99.0f && d2 < 101.0f) near_ = (sqrtf(d2) <= 10.0f);
                bool far = (i != j) && !near_;
                mm[wd] = __ballot_sync(~0u, far);
                any |= mm[wd];
            }
            if (any) {
                if (!lane) {
                    #pragma unroll
                    for (int wd = 0; wd < 16; wd++)
                        g_farmask[((size_t)(b * NN + j)) * 16 + wd] = mm[wd];
                    myj[mycnt] = (unsigned short)j;
                    g_slot[b * NN + j] = 1;          // mark dirty
                }
                mycnt++;
            }
        }
        if (!lane) sm.F.wcnt[w] = mycnt;
        __syncthreads();
        if (tid == 0) {
            int tot = 0;
            #pragma unroll
            for (int q = 0; q < 8; q++) tot += sm.F.wcnt[q];
            g_ndH[fb] = tot;
        }
        if (!lane && mycnt) {
            int off = 0;
            for (int q = 0; q < w; q++) off += sm.F.wcnt[q];
            for (int k = 0; k < mycnt; k++)
                g_dirtyJH[fb][off + k] = myj[k];
        }
    }
}

// ---------------- helpers -----------------------------------------------------
__device__ __forceinline__ int nd_total() {
    int a = 0;
    for (int h = 0; h < 128; h++) a += g_ndH[h];
    return a;
}
__device__ __forceinline__ int find_dirty(int e, int& b) {
    int acc = 0;
    for (int h = 0; h < 128; h++) {
        int c = g_ndH[h];
        if (e < acc + c) { b = h >> 1; return b * NN + g_dirtyJH[h][e - acc]; }
        acc += c;
    }
    return 0;
}

// ---------------- K2: GIN1 over work rows (ILP-4 GEMV) ------------------------
__global__ __launch_bounds__(256)
void gin1_kernel(const float* __restrict__ g1w1, const float* __restrict__ g1b1,
                 const float* __restrict__ g1w2, const float* __restrict__ g1b2)
{
    __shared__ __align__(16) float x38[40];
    __shared__ __align__(16) float y[256];
    __shared__ int s_nD;
    int tid = threadIdx.x;
    if (tid == 0) s_nD = nd_total();
    __syncthreads();
    int nW = 64 + s_nD;

    for (int row = blockIdx.x; row < nW; row += gridDim.x) {
        if (tid < DNODE) {
            float v = 0.0f;
            int b = (row < 64) ? row : 0;
            if (row >= 64) { int tmp; int tok = find_dirty(row - 64, tmp); b = tmp;
                #pragma unroll
                for (int p = 0; p < 16; p++) v += g_S0part[b * 16 + p][tid];
                for (int wd = 0; wd < 16; wd++) {
                    unsigned m = g_farmask[(size_t)tok * 16 + wd];
                    while (m) {
                        int i = wd * 32 + __ffs(m) - 1; m &= m - 1;
                        v -= g_node[((size_t)b * NN + i) * DNODE + tid];
                    }
                }
            } else {
                #pragma unroll
                for (int p = 0; p < 16; p++) v += g_S0part[b * 16 + p][tid];
            }
            x38[tid] = v;
        }
        __syncthreads();
        // layer 1: K=38
        {
            const float* wr = g1w1 + tid * DNODE;
            float a0 = 0.f, a1 = 0.f;
            #pragma unroll
            for (int k = 0; k < 19; k++) {
                a0 += wr[k] * x38[k];
                a1 += wr[19 + k] * x38[19 + k];
            }
            y[tid] = fmaxf(a0 + a1 + g1b1[tid], 0.0f);
        }
        __syncthreads();
        // layer 2: K=256 ILP-4
        {
            const float4* wr = (const float4*)(g1w2 + (size_t)tid * HH);
            const float4* s4 = (const float4*)y;
            float a0 = 0.f, a1 = 0.f, a2 = 0.f, a3 = 0.f;
            #pragma unroll
            for (int q = 0; q < 16; q++) {
                float4 w0 = wr[q],      x0 = s4[q];
                float4 w1 = wr[q + 16], x1 = s4[q + 16];
                float4 w2 = wr[q + 32], x2 = s4[q + 32];
                float4 w3 = wr[q + 48], x3 = s4[q + 48];
                a0 += w0.x * x0.x + w0.y * x0.y + w0.z * x0.z + w0.w * x0.w;
                a1 += w1.x * x1.x + w1.y * x1.y + w1.z * x1.z + w1.w * x1.w;
                a2 += w2.x * x2.x + w2.y * x2.y + w2.z * x2.z + w2.w * x2.w;
                a3 += w3.x * x3.x + w3.y * x3.y + w3.z * x3.z + w3.w * x3.w;
            }
            size_t orow = (row < 64) ? (size_t)row
                                     : (size_t)(64 + [&]{ int tb; return find_dirty(row - 64, tb); }());
            g_h1[orow * HH + tid] = fmaxf((a0 + a1) + (a2 + a3) + g1b2[tid], 0.0f);
        }
        __syncthreads();
    }
}

// ---------------- K3: S1 inline + GIN2 + transformer + head + scatter ---------
__global__ __launch_bounds__(256)
void rest_kernel(const float* __restrict__ g2w1, const float* __restrict__ g2b1,
                 const float* __restrict__ g2w2, const float* __restrict__ g2b2,
                 const float* __restrict__ t_in_w, const float* __restrict__ t_in_b,
                 const float* __restrict__ t_out_w, const float* __restrict__ t_out_b,
                 const float* __restrict__ t_ln1_g, const float* __restrict__ t_ln1_b,
                 const float* __restrict__ t_ff1_w, const float* __restrict__ t_ff1_b,
                 const float* __restrict__ t_ff2_w, const float* __restrict__ t_ff2_b,
                 const float* __restrict__ t_ln2_g, const float* __restrict__ t_ln2_b,
                 const float* __restrict__ fc_w, const float* __restrict__ fc_b,
                 float* __restrict__ out)
{
    __shared__ __align__(16) float X[256];
    __shared__ __align__(16) float T1[256];
    __shared__ __align__(16) float T2[256];
    __shared__ float red[16];
    __shared__ float out5[5];
    __shared__ int s_nD;
    int tid = threadIdx.x, w = tid >> 5, lane = tid & 31;
    if (tid == 0) s_nD = nd_total();
    __syncthreads();
    int nW = 64 + s_nD;

    auto gemv = [&](const float* src, float* dst, const float* W,
                    const float* bias, bool relu) {
        const float4* wr = (const float4*)(W + (size_t)tid * HH);
        const float4* s4 = (const float4*)src;
        float a0 = 0.f, a1 = 0.f, a2 = 0.f, a3 = 0.f;
        #pragma unroll
        for (int q = 0; q < 16; q++) {
            float4 w0 = wr[q],      x0 = s4[q];
            float4 w1 = wr[q + 16], x1 = s4[q + 16];
            float4 w2 = wr[q + 32], x2 = s4[q + 32];
            float4 w3 = wr[q + 48], x3 = s4[q + 48];
            a0 += w0.x * x0.x + w0.y * x0.y + w0.z * x0.z + w0.w * x0.w;
            a1 += w1.x * x1.x + w1.y * x1.y + w1.z * x1.z + w1.w * x1.w;
            a2 += w2.x * x2.x + w2.y * x2.y + w2.z * x2.z + w2.w * x2.w;
            a3 += w3.x * x3.x + w3.y * x3.y + w3.z * x3.z + w3.w * x3.w;
        }
        float a = (a0 + a1) + (a2 + a3) + bias[tid];
        dst[tid] = relu ? fmaxf(a, 0.f) : a;
        __syncthreads();
    };
    auto ln_row = [&](float* xv, const float* yv, const float* gg, const float* bb) {
        float v = xv[tid] + yv[tid];
        float s = v;
        #pragma unroll
        for (int off = 16; off; off >>= 1) s += __shfl_xor_sync(~0u, s, off);
        if (!lane) red[w] = s;
        __syncthreads();
        float tot = 0.f;
        #pragma unroll
        for (int q = 0; q < 8; q++) tot += red[q];
        float mean = tot * (1.0f / 256.0f);
        float d = v - mean;
        float s2 = d * d;
        #pragma unroll
        for (int off = 16; off; off >>= 1) s2 += __shfl_xor_sync(~0u, s2, off);
        if (!lane) red[8 + w] = s2;
        __syncthreads();
        float tot2 = 0.f;
        #pragma unroll
        for (int q = 0; q < 8; q++) tot2 += red[8 + q];
        float var = tot2 * (1.0f / 256.0f);
        xv[tid] = d / sqrtf(var + 1e-5f) * gg[tid] + bb[tid];
        __syncthreads();
    };
    // S1[b] for this thread's feature: (512-nd)*u + sum of batch-b dirty h1
    auto s1_of = [&](int b) {
        int nd = g_ndH[2 * b] + g_ndH[2 * b + 1];
        float s = (float)(NN - nd) * g_h1[(size_t)b * HH + tid];
        #pragma unroll 1
        for (int h = 2 * b; h <= 2 * b + 1; h++) {
            int c = g_ndH[h];
            for (int k = 0; k < c; k++) {
                int tok = b * NN + g_dirtyJH[h][k];
                s += g_h1[(size_t)(64 + tok) * HH + tid];
            }
        }
        return s;
    };

    for (int row = blockIdx.x; row < nW; row += gridDim.x) {
        int b, tok = -1;
        if (row < 64) {
            b = row;
            X[tid] = s1_of(b);
        } else {
            tok = find_dirty(row - 64, b);
            float v = s1_of(b);
            for (int wd = 0; wd < 16; wd++) {
                unsigned m = g_farmask[(size_t)tok * 16 + wd];
                while (m) {
                    int i = wd * 32 + __ffs(m) - 1; m &= m - 1;
                    v -= g_h1[(size_t)(64 + b * NN + i) * HH + tid];
                }
            }
            X[tid] = v;
        }
        __syncthreads();

        gemv(X, T1, g2w1, g2b1, true);
        gemv(T1, X, g2w2, g2b2, true);

        #pragma unroll 1
        for (int l = 0; l < 2; l++) {
            const float* Wv  = t_in_w + (size_t)l * 768 * HH + (size_t)512 * HH;
            const float* bv  = t_in_b + (size_t)l * 768 + 512;
            const float* Wo  = t_out_w + (size_t)l * HH * HH;
            const float* bo  = t_out_b + (size_t)l * HH;
            const float* W1  = t_ff1_w + (size_t)l * HH * HH;
            const float* b1  = t_ff1_b + (size_t)l * HH;
            const float* W2  = t_ff2_w + (size_t)l * HH * HH;
            const float* b2  = t_ff2_b + (size_t)l * HH;
            gemv(X,  T1, Wv, bv, false);
            gemv(T1, T2, Wo, bo, false);
            ln_row(X, T2, t_ln1_g + (size_t)l * HH, t_ln1_b + (size_t)l * HH);
            gemv(X,  T1, W1, b1, true);
            gemv(T1, T2, W2, b2, false);
            ln_row(X, T2, t_ln2_g + (size_t)l * HH, t_ln2_b + (size_t)l * HH);
        }

        if (w < 5) {
            const float* wr = fc_w + w * HH;
            float s = 0.f;
            #pragma unroll
            for (int q = 0; q < 8; q++) s += X[lane + 32 * q] * wr[lane + 32 * q];
            #pragma unroll
            for (int off = 16; off; off >>= 1) s += __shfl_xor_sync(~0u, s, off);
            if (!lane) out5[w] = s + fc_b[w];
        }
        __syncthreads();

        if (row < 64) {
            for (int t = tid; t < NN; t += 256) {
                int tk = b * NN + t;
                if (g_slot[tk] < 0) {
                    float* o = out + (size_t)tk * 5;
                    o[0] = out5[0]; o[1] = out5[1]; o[2] = out5[2];
                    o[3] = out5[3]; o[4] = out5[4];
                }
            }
        } else {
            if (tid < 5) out[(size_t)tok * 5 + tid] = out5[tid];
        }
        __syncthreads();
    }
}

// ---------------- launch ------------------------------------------------------
extern "C" void kernel_launch(void* const* d_in, const int* in_sizes, int n_in,
                              void* d_out, int out_size)
{
    const float* data   = (const float*)d_in[0];
    const float* lw1    = (const float*)d_in[1];
    const float* lb1    = (const float*)d_in[2];
    const float* lw2    = (const float*)d_in[3];
    const float* lb2    = (const float*)d_in[4];
    const float* g1w1   = (const float*)d_in[5];
    const float* g1b1   = (const float*)d_in[6];
    const float* g1w2   = (const float*)d_in[7];
    const float* g1b2   = (const float*)d_in[8];
    const float* g2w1   = (const float*)d_in[9];
    const float* g2b1   = (const float*)d_in[10];
    const float* g2w2   = (const float*)d_in[11];
    const float* g2b2   = (const float*)d_in[12];
    const float* t_in_w = (const float*)d_in[13];
    const float* t_in_b = (const float*)d_in[14];
    const float* t_out_w= (const float*)d_in[15];
    const float* t_out_b= (const float*)d_in[16];
    const float* t_ln1_g= (const float*)d_in[17];
    const float* t_ln1_b= (const float*)d_in[18];
    const float* t_ff1_w= (const float*)d_in[19];
    const float* t_ff1_b= (const float*)d_in[20];
    const float* t_ff2_w= (const float*)d_in[21];
    const float* t_ff2_b= (const float*)d_in[22];
    const float* t_ln2_g= (const float*)d_in[23];
    const float* t_ln2_b= (const float*)d_in[24];
    const float* fc_w   = (const float*)d_in[25];
    const float* fc_b   = (const float*)d_in[26];
    float* out = (float*)d_out;

    void* slotp;
    cudaGetSymbolAddress(&slotp, g_slot);
    cudaMemsetAsync(slotp, 0xFF, sizeof(int) * TOKENS);   // all clean (-1)

    k1_kernel<<<NTILE + 128, 256>>>(data, lw1, lb1, lw2, lb2);
    gin1_kernel<<<256, 256>>>(g1w1, g1b1, g1w2, g1b2);
    rest_kernel<<<256, 256>>>(g2w1, g2b1, g2w2, g2b2,
                              t_in_w, t_in_b, t_out_w, t_out_b,
                              t_ln1_g, t_ln1_b, t_ff1_w, t_ff1_b,
                              t_ff2_w, t_ff2_b, t_ln2_g, t_ln2_b,
                              fc_w, fc_b, out);
    (void)in_sizes; (void)n_in; (void)out_size;
}